// round 9
// baseline (speedup 1.0000x reference)
#include <cuda_runtime.h>
#include <cstdint>

#define NGROUPS 512   // B*S/16
#define NSLOTS  64    // E*Sets
#define DDIM    512
#define TTOK    16
#define FDIM    32

typedef unsigned long long ull;
union U2 { ull u; float2 f; };

// packed fp32x2 FMA (route kernel)
__device__ __forceinline__ void ffma2(ull& d, ull a, ull b) {
    asm("fma.rn.f32x2 %0, %1, %2, %0;" : "+l"(d) : "l"(a), "l"(b));
}
__device__ __forceinline__ ull bcast2(float x) {
    ull r; asm("mov.b64 %0, {%1, %1};" : "=l"(r) : "f"(x)); return r;
}

__device__ int g_winners[NGROUPS * NSLOTS];

// ---------------------------------------------------------------------------
// tf32 helpers
// ---------------------------------------------------------------------------
__device__ __forceinline__ uint32_t tf32hi(float v) {
    uint32_t r; asm("cvt.rna.tf32.f32 %0, %1;" : "=r"(r) : "f"(v)); return r;
}
__device__ __forceinline__ void split_tf32(float v, uint32_t& h, uint32_t& l) {
    h = tf32hi(v);
    l = tf32hi(v - __uint_as_float(h));
}
__device__ __forceinline__ ull packu(uint32_t lo, uint32_t hi) {
    return (ull)lo | ((ull)hi << 32);
}
__device__ __forceinline__ void mma8(float* c, uint32_t a0, uint32_t a1,
                                     uint32_t a2, uint32_t a3,
                                     uint32_t b0, uint32_t b1) {
    asm volatile("mma.sync.aligned.m16n8k8.row.col.f32.tf32.tf32.f32 "
                 "{%0,%1,%2,%3}, {%4,%5,%6,%7}, {%8,%9}, {%0,%1,%2,%3};"
                 : "+f"(c[0]), "+f"(c[1]), "+f"(c[2]), "+f"(c[3])
                 : "r"(a0), "r"(a1), "r"(a2), "r"(a3), "r"(b0), "r"(b1));
}
__device__ __forceinline__ uint32_t ulo(ull v) { return (uint32_t)v; }
__device__ __forceinline__ uint32_t uhi(ull v) { return (uint32_t)(v >> 32); }

// ---------------------------------------------------------------------------
// Kernel 1: routing (unchanged — proven exact; ~2us). Zero-inits out.
// ---------------------------------------------------------------------------
__global__ __launch_bounds__(256) void k_route(const float* __restrict__ x,
                                               const float* __restrict__ ctrl,
                                               float* __restrict__ out)
{
    extern __shared__ float sm[];
    float* xs   = sm;
    float* part = sm + 8192;
    float* ls   = sm + 12288;
    double* dred = (double*)(sm + 13312);
    __shared__ int sflags[64];
    __shared__ int swin[64];
    __shared__ int snf;
    __shared__ double dlog[16];

    const int G   = blockIdx.x;
    const int tid = threadIdx.x;
    if (tid == 0) snf = 0;

    const float4* src = (const float4*)(x + (size_t)G * 8192);
    float4* dst = (float4*)(out + (size_t)G * 8192);
    float4* xs4 = (float4*)xs;
    const float4 z4 = make_float4(0.f, 0.f, 0.f, 0.f);
    for (int i = tid; i < 2048; i += 256) { xs4[i] = src[i]; dst[i] = z4; }
    __syncthreads();

    {
        const int sq = tid & 15;
        const int tq = (tid >> 4) & 3;
        const int ks = tid >> 6;
        const int kbase = ks * 128;
        U2 acc[4][2];
        #pragma unroll
        for (int t = 0; t < 4; ++t) { acc[t][0].u = 0ull; acc[t][1].u = 0ull; }
        const float* cbase = ctrl + sq * 4;
        const float* x0 = xs + tq * 4 * DDIM;
        for (int kk = 0; kk < 128; kk += 4) {
            const int k = kbase + kk;
            ulonglong2 w[4];
            #pragma unroll
            for (int j = 0; j < 4; ++j)
                w[j] = __ldg((const ulonglong2*)(cbase + (size_t)(k + j) * 64));
            float xv[4][4];
            #pragma unroll
            for (int t = 0; t < 4; ++t)
                *(float4*)&xv[t][0] = *(const float4*)(x0 + t * DDIM + k);
            #pragma unroll
            for (int j = 0; j < 4; ++j) {
                #pragma unroll
                for (int t = 0; t < 4; ++t) {
                    ull xb = bcast2(xv[t][j]);
                    ffma2(acc[t][0].u, xb, w[j].x);
                    ffma2(acc[t][1].u, xb, w[j].y);
                }
            }
        }
        #pragma unroll
        for (int t = 0; t < 4; ++t) {
            part[tid * 16 + t * 4 + 0] = acc[t][0].f.x;
            part[tid * 16 + t * 4 + 1] = acc[t][0].f.y;
            part[tid * 16 + t * 4 + 2] = acc[t][1].f.x;
            part[tid * 16 + t * 4 + 3] = acc[t][1].f.y;
        }
    }
    __syncthreads();

    {
        const int s   = tid & 63;
        const int tq2 = tid >> 6;
        const int sq2 = s >> 2, sl = s & 3;
        const float step = 1e-6f / 15.f;
        #pragma unroll
        for (int tl = 0; tl < 4; ++tl) {
            float v = 0.f;
            #pragma unroll
            for (int c = 0; c < 4; ++c)
                v += part[(c * 64 + tq2 * 16 + sq2) * 16 + tl * 4 + sl];
            const int t = tq2 * 4 + tl;
            ls[s * 16 + t] = v + step * (float)t;
        }
    }
    __syncthreads();

    if (tid < 64) {
        const int s = tid;
        float best = -3.4e38f, second = -3.4e38f;
        int bi = 0;
        #pragma unroll
        for (int t = 0; t < TTOK; ++t) {
            float v = ls[s * 16 + t];
            if (v >= best) { second = best; best = v; bi = t; }
            else if (v > second) { second = v; }
        }
        swin[s] = bi;
        if (best - second < 2e-5f) { int p = atomicAdd(&snf, 1); sflags[p] = s; }
    }
    __syncthreads();

    const int nf = snf;
    for (int i = 0; i < nf; ++i) {
        const int s = sflags[i];
        const int t = tid >> 4, j = tid & 15;
        double a = 0.0;
        const float* xr = xs + t * DDIM + j * 32;
        const float* cp = ctrl + (size_t)(j * 32) * 64 + s;
        #pragma unroll 8
        for (int k = 0; k < 32; ++k)
            a += (double)xr[k] * (double)__ldg(cp + (size_t)k * 64);
        dred[t * 16 + j] = a;
        __syncthreads();
        if (tid < 16) {
            double tot = 0.0;
            #pragma unroll
            for (int j2 = 0; j2 < 16; ++j2) tot += dred[tid * 16 + j2];
            dlog[tid] = tot + (double)tid * (1e-6 / 15.0);
        }
        __syncthreads();
        if (tid == 0) {
            double best = -1e300; int bi = 0;
            #pragma unroll
            for (int t2 = 0; t2 < TTOK; ++t2)
                if (dlog[t2] >= best) { best = dlog[t2]; bi = t2; }
            swin[s] = bi;
        }
        __syncthreads();
    }
    if (tid < 64) g_winners[G * 64 + tid] = swin[tid];
}

// ---------------------------------------------------------------------------
// Kernel 2: tf32 mma.sync expert with register double-buffering.
// CTA = (slot, 64 groups). Split precision (hi/lo tf32, 3 mma per logical).
// Smem layouts (ull, pairing P=(k>>3)*4+(k&3), word = (k, k+4)):
//   rowb @0          (256 B)
//   B1h  @256   [32][37] (9472)    B1l @9728
//   Yh   @19200 [16][69] (8832)    Yl  @28032
//   Xh   @36864 [32][69] (17664)   Xl  @54528   (B2h/B2l [16][133] alias)
// total 72192 B
// ---------------------------------------------------------------------------
#define OFF_ROWB 0
#define OFF_B1H  256
#define OFF_B1L  9728
#define OFF_YH   19200
#define OFF_YL   28032
#define OFF_XH   36864
#define OFF_XL   54528
#define SMEM2    72192

__global__ __launch_bounds__(256, 3) void k_expert(const float* __restrict__ x,
                                                   const float* __restrict__ f1,
                                                   const float* __restrict__ f2,
                                                   float* __restrict__ out)
{
    extern __shared__ __align__(16) char smraw[];
    int*      rowb  = (int*)(smraw + OFF_ROWB);
    ull*      B1h_u = (ull*)(smraw + OFF_B1H);
    ull*      B1l_u = (ull*)(smraw + OFF_B1L);
    uint32_t* Yh32  = (uint32_t*)(smraw + OFF_YH);
    uint32_t* Yl32  = (uint32_t*)(smraw + OFF_YL);
    ull*      Yh_u  = (ull*)(smraw + OFF_YH);
    ull*      Yl_u  = (ull*)(smraw + OFF_YL);
    ull*      Xh_u  = (ull*)(smraw + OFF_XH);
    ull*      Xl_u  = (ull*)(smraw + OFF_XL);
    ull*      B2h_u = (ull*)(smraw + OFF_XH);
    ull*      B2l_u = (ull*)(smraw + OFF_XL);

    const int slot = blockIdx.y;
    const int g0   = blockIdx.x * 64;
    const int tid  = threadIdx.x;
    const int wid  = tid >> 5;
    const int lane = tid & 31;
    const int gq   = lane >> 2;   // fragment row group 0..7
    const int c4   = lane & 3;    // fragment col group 0..3

    if (tid < 64) {
        const int gg = g0 + tid;
        rowb[tid] = (gg * TTOK + g_winners[gg * 64 + slot]) * DDIM;
    }
    __syncthreads();

    // ================= GEMM1: C[64,32] = X[64,512] @ f1slc[512,32] =========
    const int mt  = wid & 3;
    const int m0  = mt * 16;
    const int ntb = (wid >> 2) * 2;

    // staging assignments
    const int xr    = tid >> 2;             // X row 0..63
    const int xkq   = (tid & 3) * 16;       // X k base (16 k's)
    const int f1pb  = tid >> 3;             // B1 pair index 0..31
    const int f1f0  = (tid & 7) * 4;        // B1 f base (4 f's)
    const int f1klo = ((f1pb >> 2) << 3) | (f1pb & 3);
    const float* xrow = x + rowb[xr];
    const float* f1b  = f1 + slot * 32 + f1f0;

    float4 xv[4];
    float4 w_lo, w_hi;
    // preload chunk 0
    {
        const float* xp = xrow + xkq;
        #pragma unroll
        for (int q = 0; q < 4; ++q) xv[q] = __ldg((const float4*)(xp + q * 4));
        const float* fp = f1b + (size_t)f1klo * 2048;
        w_lo = __ldg((const float4*)fp);
        w_hi = __ldg((const float4*)(fp + 4 * 2048));
    }

    float acc1[2][4];
    #pragma unroll
    for (int j = 0; j < 2; ++j)
        #pragma unroll
        for (int e = 0; e < 4; ++e) acc1[j][e] = 0.f;

    for (int cb = 0; cb < 8; ++cb) {
        // ---- stage current chunk from registers (paired ST.64)
        {
            const float* xvf = (const float*)xv;
            #pragma unroll
            for (int j = 0; j < 8; ++j) {
                const int lk = ((j >> 2) << 3) | (j & 3);   // 0..3, 8..11
                const int k_lo = xkq + lk;
                const int P = ((k_lo >> 3) << 2) | (k_lo & 3);
                uint32_t h0, l0, h1, l1;
                split_tf32(xvf[lk], h0, l0);
                split_tf32(xvf[lk + 4], h1, l1);
                Xh_u[P * 69 + xr] = packu(h0, h1);
                Xl_u[P * 69 + xr] = packu(l0, l1);
            }
            const float* wl = (const float*)&w_lo;
            const float* wh = (const float*)&w_hi;
            #pragma unroll
            for (int e = 0; e < 4; ++e) {
                uint32_t h0, l0, h1, l1;
                split_tf32(wl[e], h0, l0);
                split_tf32(wh[e], h1, l1);
                B1h_u[f1pb * 37 + f1f0 + e] = packu(h0, h1);
                B1l_u[f1pb * 37 + f1f0 + e] = packu(l0, l1);
            }
        }
        __syncthreads();

        // ---- prefetch next chunk into registers
        if (cb < 7) {
            const int kb = (cb + 1) * 64;
            const float* xp = xrow + kb + xkq;
            #pragma unroll
            for (int q = 0; q < 4; ++q) xv[q] = __ldg((const float4*)(xp + q * 4));
            const float* fp = f1b + (size_t)(kb + f1klo) * 2048;
            w_lo = __ldg((const float4*)fp);
            w_hi = __ldg((const float4*)(fp + 4 * 2048));
        }

        // ---- compute: 8 k-steps x 2 n-tiles x 3 mma
        #pragma unroll
        for (int k8 = 0; k8 < 8; ++k8) {
            const int Pb = k8 * 4 + c4;
            const ull ah0 = Xh_u[Pb * 69 + m0 + gq];
            const ull ah1 = Xh_u[Pb * 69 + m0 + 8 + gq];
            const ull al0 = Xl_u[Pb * 69 + m0 + gq];
            const ull al1 = Xl_u[Pb * 69 + m0 + 8 + gq];
            #pragma unroll
            for (int j = 0; j < 2; ++j) {
                const int n0 = (ntb + j) * 8;
                const ull bh = B1h_u[Pb * 37 + n0 + gq];
                const ull bl = B1l_u[Pb * 37 + n0 + gq];
                mma8(acc1[j], ulo(ah0), ulo(ah1), uhi(ah0), uhi(ah1), ulo(bh), uhi(bh));
                mma8(acc1[j], ulo(ah0), ulo(ah1), uhi(ah0), uhi(ah1), ulo(bl), uhi(bl));
                mma8(acc1[j], ulo(al0), ulo(al1), uhi(al0), uhi(al1), ulo(bh), uhi(bh));
            }
        }
        __syncthreads();
    }

    // --- relu + split -> Y (paired over f; scalar 32b writes, small) -------
    #pragma unroll
    for (int j = 0; j < 2; ++j) {
        const int n0 = (ntb + j) * 8;
        #pragma unroll
        for (int e = 0; e < 4; ++e) {
            const int f   = n0 + 2 * c4 + (e & 1);
            const int row = m0 + gq + ((e >> 1) << 3);
            const int P   = ((f >> 3) << 2) | (f & 3);
            const int hf  = (f >> 2) & 1;
            uint32_t h, l; split_tf32(fmaxf(acc1[j][e], 0.f), h, l);
            const int idx = (P * 69 + row) * 2 + hf;
            Yh32[idx] = h; Yl32[idx] = l;
        }
    }

    // ---- prefetch f2 chunk nc=0 (into regs; B2 region still holds X — ok)
    const int b2pb  = tid >> 4;             // pair index 0..15
    const int b2n0  = (tid & 15) * 8;       // 8 n's
    const int b2klo = ((b2pb >> 2) << 3) | (b2pb & 3);
    const float* f2b = f2 + (size_t)slot * (FDIM * DDIM) + (size_t)b2klo * DDIM + b2n0;
    float4 bv[4];
    {
        #pragma unroll
        for (int q = 0; q < 2; ++q) {
            bv[q]     = __ldg((const float4*)(f2b + q * 4));
            bv[q + 2] = __ldg((const float4*)(f2b + 4 * DDIM + q * 4));
        }
    }
    __syncthreads();

    // ---- preload Y fragments once (k = 0..31 entirely)
    ull yh0[4], yh1[4], yl0[4], yl1[4];
    #pragma unroll
    for (int k8 = 0; k8 < 4; ++k8) {
        const int Pb = k8 * 4 + c4;
        yh0[k8] = Yh_u[Pb * 69 + m0 + gq];
        yh1[k8] = Yh_u[Pb * 69 + m0 + 8 + gq];
        yl0[k8] = Yl_u[Pb * 69 + m0 + gq];
        yl1[k8] = Yl_u[Pb * 69 + m0 + 8 + gq];
    }

    // ================= GEMM2: Out[64,512] = Y[64,32] @ f2slc[32,512] =======
    const int nh = wid >> 2;
    for (int nc = 0; nc < 4; ++nc) {
        // ---- stage B2 from registers (paired ST.64)
        {
            const float* blo = (const float*)&bv[0];   // k_lo, 8 n
            const float* bhi = (const float*)&bv[2];   // k_hi, 8 n
            #pragma unroll
            for (int e = 0; e < 8; ++e) {
                uint32_t h0, l0, h1, l1;
                split_tf32(blo[e], h0, l0);
                split_tf32(bhi[e], h1, l1);
                B2h_u[b2pb * 133 + b2n0 + e] = packu(h0, h1);
                B2l_u[b2pb * 133 + b2n0 + e] = packu(l0, l1);
            }
        }
        __syncthreads();

        // ---- prefetch next nc
        if (nc < 3) {
            const float* fp = f2b + (nc + 1) * 128;
            #pragma unroll
            for (int q = 0; q < 2; ++q) {
                bv[q]     = __ldg((const float4*)(fp + q * 4));
                bv[q + 2] = __ldg((const float4*)(fp + 4 * DDIM + q * 4));
            }
        }

        // ---- 8 n-tiles of 8; compute + immediate atomic scatter
        #pragma unroll 2
        for (int nt = 0; nt < 8; ++nt) {
            const int n0 = nh * 64 + nt * 8;
            float acc[4] = {0.f, 0.f, 0.f, 0.f};
            #pragma unroll
            for (int k8 = 0; k8 < 4; ++k8) {
                const int Pb = k8 * 4 + c4;
                const ull bh = B2h_u[Pb * 133 + n0 + gq];
                const ull bl = B2l_u[Pb * 133 + n0 + gq];
                mma8(acc, ulo(yh0[k8]), ulo(yh1[k8]), uhi(yh0[k8]), uhi(yh1[k8]), ulo(bh), uhi(bh));
                mma8(acc, ulo(yh0[k8]), ulo(yh1[k8]), uhi(yh0[k8]), uhi(yh1[k8]), ulo(bl), uhi(bl));
                mma8(acc, ulo(yl0[k8]), ulo(yl1[k8]), uhi(yl0[k8]), uhi(yl1[k8]), ulo(bh), uhi(bh));
            }
            const int d = nc * 128 + n0 + 2 * c4;
            atomicAdd((float2*)(out + rowb[m0 + gq]     + d), make_float2(acc[0], acc[1]));
            atomicAdd((float2*)(out + rowb[m0 + 8 + gq] + d), make_float2(acc[2], acc[3]));
        }
        __syncthreads();
    }
}

// ---------------------------------------------------------------------------
extern "C" void kernel_launch(void* const* d_in, const int* in_sizes, int n_in,
                              void* d_out, int out_size)
{
    (void)in_sizes; (void)n_in; (void)out_size;
    const float* x    = (const float*)d_in[0];
    const float* ctrl = (const float*)d_in[1];
    const float* f1   = (const float*)d_in[2];
    const float* f2   = (const float*)d_in[3];
    float* out = (float*)d_out;

    const int smem1 = 13312 * 4 + 2048;   // 55296
    cudaFuncSetAttribute(k_route,  cudaFuncAttributeMaxDynamicSharedMemorySize, smem1);
    cudaFuncSetAttribute(k_expert, cudaFuncAttributeMaxDynamicSharedMemorySize, SMEM2);

    k_route<<<NGROUPS, 256, smem1>>>(x, ctrl, out);
    k_expert<<<dim3(8, 64), 256, SMEM2>>>(x, f1, f2, out);
}

// round 10
// speedup vs baseline: 1.6633x; 1.6633x over previous
#include <cuda_runtime.h>
#include <cstdint>

#define NGROUPS 512   // B*S/16
#define NSLOTS  64    // E*Sets
#define DDIM    512
#define TTOK    16
#define FDIM    32

typedef unsigned long long ull;
union U2 { ull u; float2 f; };

// packed fp32x2 FMA (route kernel)
__device__ __forceinline__ void ffma2(ull& d, ull a, ull b) {
    asm("fma.rn.f32x2 %0, %1, %2, %0;" : "+l"(d) : "l"(a), "l"(b));
}
__device__ __forceinline__ ull bcast2(float x) {
    ull r; asm("mov.b64 %0, {%1, %1};" : "=l"(r) : "f"(x)); return r;
}

__device__ int g_winners[NGROUPS * NSLOTS];

// ---------------------------------------------------------------------------
// bf16 split helpers
// ---------------------------------------------------------------------------
// pack (v0 -> low bf16, v1 -> high bf16); PTX cvt order: d, hi_src, lo_src
__device__ __forceinline__ uint32_t bf2_of(float v0, float v1) {
    uint32_t r;
    asm("cvt.rn.bf16x2.f32 %0, %1, %2;" : "=r"(r) : "f"(v1), "f"(v0));
    return r;
}
// split (v0,v1) into bf16 hi-pair (low32) and residual lo-pair (high32)
__device__ __forceinline__ ull splitpack(float v0, float v1) {
    const uint32_t h = bf2_of(v0, v1);
    const float r0 = v0 - __uint_as_float(h << 16);
    const float r1 = v1 - __uint_as_float(h & 0xffff0000u);
    const uint32_t l = bf2_of(r0, r1);
    return (ull)h | ((ull)l << 32);
}
__device__ __forceinline__ void mma16(float* c, uint32_t a0, uint32_t a1,
                                      uint32_t a2, uint32_t a3,
                                      uint32_t b0, uint32_t b1) {
    asm volatile("mma.sync.aligned.m16n8k16.row.col.f32.bf16.bf16.f32 "
                 "{%0,%1,%2,%3}, {%4,%5,%6,%7}, {%8,%9}, {%0,%1,%2,%3};"
                 : "+f"(c[0]), "+f"(c[1]), "+f"(c[2]), "+f"(c[3])
                 : "r"(a0), "r"(a1), "r"(a2), "r"(a3), "r"(b0), "r"(b1));
}
__device__ __forceinline__ uint32_t ulo(ull v) { return (uint32_t)v; }
__device__ __forceinline__ uint32_t uhi(ull v) { return (uint32_t)(v >> 32); }

// ---------------------------------------------------------------------------
// Kernel 1: routing (unchanged — proven exact; ~2us). Zero-inits out.
// ---------------------------------------------------------------------------
__global__ __launch_bounds__(256) void k_route(const float* __restrict__ x,
                                               const float* __restrict__ ctrl,
                                               float* __restrict__ out)
{
    extern __shared__ float sm[];
    float* xs   = sm;
    float* part = sm + 8192;
    float* ls   = sm + 12288;
    double* dred = (double*)(sm + 13312);
    __shared__ int sflags[64];
    __shared__ int swin[64];
    __shared__ int snf;
    __shared__ double dlog[16];

    const int G   = blockIdx.x;
    const int tid = threadIdx.x;
    if (tid == 0) snf = 0;

    const float4* src = (const float4*)(x + (size_t)G * 8192);
    float4* dst = (float4*)(out + (size_t)G * 8192);
    float4* xs4 = (float4*)xs;
    const float4 z4 = make_float4(0.f, 0.f, 0.f, 0.f);
    for (int i = tid; i < 2048; i += 256) { xs4[i] = src[i]; dst[i] = z4; }
    __syncthreads();

    {
        const int sq = tid & 15;
        const int tq = (tid >> 4) & 3;
        const int ks = tid >> 6;
        const int kbase = ks * 128;
        U2 acc[4][2];
        #pragma unroll
        for (int t = 0; t < 4; ++t) { acc[t][0].u = 0ull; acc[t][1].u = 0ull; }
        const float* cbase = ctrl + sq * 4;
        const float* x0 = xs + tq * 4 * DDIM;
        for (int kk = 0; kk < 128; kk += 4) {
            const int k = kbase + kk;
            ulonglong2 w[4];
            #pragma unroll
            for (int j = 0; j < 4; ++j)
                w[j] = __ldg((const ulonglong2*)(cbase + (size_t)(k + j) * 64));
            float xv[4][4];
            #pragma unroll
            for (int t = 0; t < 4; ++t)
                *(float4*)&xv[t][0] = *(const float4*)(x0 + t * DDIM + k);
            #pragma unroll
            for (int j = 0; j < 4; ++j) {
                #pragma unroll
                for (int t = 0; t < 4; ++t) {
                    ull xb = bcast2(xv[t][j]);
                    ffma2(acc[t][0].u, xb, w[j].x);
                    ffma2(acc[t][1].u, xb, w[j].y);
                }
            }
        }
        #pragma unroll
        for (int t = 0; t < 4; ++t) {
            part[tid * 16 + t * 4 + 0] = acc[t][0].f.x;
            part[tid * 16 + t * 4 + 1] = acc[t][0].f.y;
            part[tid * 16 + t * 4 + 2] = acc[t][1].f.x;
            part[tid * 16 + t * 4 + 3] = acc[t][1].f.y;
        }
    }
    __syncthreads();

    {
        const int s   = tid & 63;
        const int tq2 = tid >> 6;
        const int sq2 = s >> 2, sl = s & 3;
        const float step = 1e-6f / 15.f;
        #pragma unroll
        for (int tl = 0; tl < 4; ++tl) {
            float v = 0.f;
            #pragma unroll
            for (int c = 0; c < 4; ++c)
                v += part[(c * 64 + tq2 * 16 + sq2) * 16 + tl * 4 + sl];
            const int t = tq2 * 4 + tl;
            ls[s * 16 + t] = v + step * (float)t;
        }
    }
    __syncthreads();

    if (tid < 64) {
        const int s = tid;
        float best = -3.4e38f, second = -3.4e38f;
        int bi = 0;
        #pragma unroll
        for (int t = 0; t < TTOK; ++t) {
            float v = ls[s * 16 + t];
            if (v >= best) { second = best; best = v; bi = t; }
            else if (v > second) { second = v; }
        }
        swin[s] = bi;
        if (best - second < 2e-5f) { int p = atomicAdd(&snf, 1); sflags[p] = s; }
    }
    __syncthreads();

    const int nf = snf;
    for (int i = 0; i < nf; ++i) {
        const int s = sflags[i];
        const int t = tid >> 4, j = tid & 15;
        double a = 0.0;
        const float* xr = xs + t * DDIM + j * 32;
        const float* cp = ctrl + (size_t)(j * 32) * 64 + s;
        #pragma unroll 8
        for (int k = 0; k < 32; ++k)
            a += (double)xr[k] * (double)__ldg(cp + (size_t)k * 64);
        dred[t * 16 + j] = a;
        __syncthreads();
        if (tid < 16) {
            double tot = 0.0;
            #pragma unroll
            for (int j2 = 0; j2 < 16; ++j2) tot += dred[tid * 16 + j2];
            dlog[tid] = tot + (double)tid * (1e-6 / 15.0);
        }
        __syncthreads();
        if (tid == 0) {
            double best = -1e300; int bi = 0;
            #pragma unroll
            for (int t2 = 0; t2 < TTOK; ++t2)
                if (dlog[t2] >= best) { best = dlog[t2]; bi = t2; }
            swin[s] = bi;
        }
        __syncthreads();
    }
    if (tid < 64) g_winners[G * 64 + tid] = swin[tid];
}

// ---------------------------------------------------------------------------
// Kernel 2: split-bf16 mma.sync (m16n8k16) expert. CTA = (slot, 64 groups).
// Each element stored in smem as one 8B word: low32 = bf16x2 hi-pair (k,k+1),
// high32 = bf16x2 residual-pair. 3 mma per logical (hh, hl, lh).
// Layouts (ull units; kp = k/2):
//   rowb @0      (256 B)
//   B1u  @256    [32 kp][36]  f1 chunk     (9216 B)
//   Yu   @9472   [64 row][20] relu'd Y     (10240 B)
//   Xu   @19712  [64 row][36] X chunk      (18432 B)   B2u [16 kp][132] alias
// total 38144 B. Strides 36/20/132 == 4 (mod 16) -> conflict-free LDS.64.
// ---------------------------------------------------------------------------
#define OFF_ROWB 0
#define OFF_B1   256
#define OFF_Y    9472
#define OFF_X    19712
#define SMEM2    38144

__global__ __launch_bounds__(256, 3) void k_expert(const float* __restrict__ x,
                                                   const float* __restrict__ f1,
                                                   const float* __restrict__ f2,
                                                   float* __restrict__ out)
{
    extern __shared__ __align__(16) char smraw[];
    int* rowb = (int*)(smraw + OFF_ROWB);
    ull* B1u  = (ull*)(smraw + OFF_B1);
    ull* Yu   = (ull*)(smraw + OFF_Y);
    ull* Xu   = (ull*)(smraw + OFF_X);
    ull* B2u  = (ull*)(smraw + OFF_X);   // alias (X dead by GEMM2)

    const int slot = blockIdx.y;
    const int g0   = blockIdx.x * 64;
    const int tid  = threadIdx.x;
    const int wid  = tid >> 5;
    const int lane = tid & 31;
    const int gq   = lane >> 2;   // fragment row group 0..7
    const int c4   = lane & 3;    // fragment col group 0..3

    if (tid < 64) {
        const int gg = g0 + tid;
        rowb[tid] = (gg * TTOK + g_winners[gg * 64 + slot]) * DDIM;
    }
    __syncthreads();

    // warp tile mapping: 4 m-tiles x 2 n-halves
    const int m0  = (wid & 3) * 16;
    const int nhb = wid >> 2;            // 0/1

    // staging assignments
    const int xr  = tid >> 2;            // X row 0..63
    const int xc4 = tid & 3;             // X kp comb (kp = xc4 + 4t)
    const int bkp = tid >> 3;            // B1 kpair 0..31
    const int bfq = (tid & 7) * 4;       // B1 f base
    const float* xrow = x + rowb[xr];
    const float* f1b  = f1 + slot * 32 + bfq;

    // preload chunk 0 (register double buffer)
    float2 xv[8];
    float4 wva, wvb;
    {
        #pragma unroll
        for (int t = 0; t < 8; ++t)
            xv[t] = __ldg((const float2*)(xrow + (xc4 + 4 * t) * 2));
        wva = __ldg((const float4*)(f1b + (size_t)(2 * bkp) * 2048));
        wvb = __ldg((const float4*)(f1b + (size_t)(2 * bkp + 1) * 2048));
    }

    float acc1[2][4];
    #pragma unroll
    for (int j = 0; j < 2; ++j)
        #pragma unroll
        for (int e = 0; e < 4; ++e) acc1[j][e] = 0.f;

    // ================= GEMM1: C[64,32] = X[64,512] @ f1slc[512,32] =========
    for (int cb = 0; cb < 8; ++cb) {
        // stage current chunk (conflict-free ST.64)
        #pragma unroll
        for (int t = 0; t < 8; ++t)
            Xu[xr * 36 + xc4 + 4 * t] = splitpack(xv[t].x, xv[t].y);
        {
            const float* a = (const float*)&wva;
            const float* b = (const float*)&wvb;
            #pragma unroll
            for (int e = 0; e < 4; ++e)
                B1u[bkp * 36 + bfq + e] = splitpack(a[e], b[e]);
        }
        __syncthreads();

        // prefetch next chunk
        if (cb < 7) {
            const int kb = (cb + 1) * 64;
            #pragma unroll
            for (int t = 0; t < 8; ++t)
                xv[t] = __ldg((const float2*)(xrow + kb + (xc4 + 4 * t) * 2));
            wva = __ldg((const float4*)(f1b + (size_t)(kb + 2 * bkp) * 2048));
            wvb = __ldg((const float4*)(f1b + (size_t)(kb + 2 * bkp + 1) * 2048));
        }

        // compute: 4 k16-steps x 2 n-tiles x 3 mma
        #pragma unroll
        for (int s = 0; s < 4; ++s) {
            const int kp = s * 8 + c4;
            const ull a0 = Xu[(m0 + gq) * 36 + kp];
            const ull a1 = Xu[(m0 + 8 + gq) * 36 + kp];
            const ull a2 = Xu[(m0 + gq) * 36 + kp + 4];
            const ull a3 = Xu[(m0 + 8 + gq) * 36 + kp + 4];
            #pragma unroll
            for (int j = 0; j < 2; ++j) {
                const int n0 = nhb * 16 + j * 8;
                const ull b0 = B1u[kp * 36 + n0 + gq];
                const ull b1 = B1u[(kp + 4) * 36 + n0 + gq];
                mma16(acc1[j], ulo(a0), ulo(a1), ulo(a2), ulo(a3), ulo(b0), ulo(b1));
                mma16(acc1[j], ulo(a0), ulo(a1), ulo(a2), ulo(a3), uhi(b0), uhi(b1));
                mma16(acc1[j], uhi(a0), uhi(a1), uhi(a2), uhi(a3), ulo(b0), ulo(b1));
            }
        }
        __syncthreads();
    }

    // --- relu + split-bf16 -> Yu[row][fpair] ------------------------------
    #pragma unroll
    for (int j = 0; j < 2; ++j) {
        const int n0 = nhb * 16 + j * 8;
        const int kp = n0 / 2 + c4;
        Yu[(m0 + gq) * 20 + kp] =
            splitpack(fmaxf(acc1[j][0], 0.f), fmaxf(acc1[j][1], 0.f));
        Yu[(m0 + 8 + gq) * 20 + kp] =
            splitpack(fmaxf(acc1[j][2], 0.f), fmaxf(acc1[j][3], 0.f));
    }

    // prefetch f2 chunk nc=0 (B2 region still holds X; regs only)
    const int b2kp = tid >> 4;            // 0..15
    const int b2n  = (tid & 15) * 8;      // 8 n's
    const float* f2b = f2 + (size_t)slot * (FDIM * DDIM)
                     + (size_t)(2 * b2kp) * DDIM + b2n;
    float4 pa0, pa1, pb0, pb1;
    pa0 = __ldg((const float4*)f2b);
    pa1 = __ldg((const float4*)(f2b + 4));
    pb0 = __ldg((const float4*)(f2b + DDIM));
    pb1 = __ldg((const float4*)(f2b + DDIM + 4));
    __syncthreads();   // Y visible; X reads done -> B2 alias safe

    // preload Y fragments (entire k=32) once
    ull y0[2], y1[2], y2[2], y3[2];
    #pragma unroll
    for (int s = 0; s < 2; ++s) {
        const int kp = s * 8 + c4;
        y0[s] = Yu[(m0 + gq) * 20 + kp];
        y1[s] = Yu[(m0 + 8 + gq) * 20 + kp];
        y2[s] = Yu[(m0 + gq) * 20 + kp + 4];
        y3[s] = Yu[(m0 + 8 + gq) * 20 + kp + 4];
    }

    // stage B2 nc=0
    {
        const float* a0p = (const float*)&pa0;
        const float* a1p = (const float*)&pa1;
        const float* b0p = (const float*)&pb0;
        const float* b1p = (const float*)&pb1;
        #pragma unroll
        for (int e = 0; e < 4; ++e) {
            B2u[b2kp * 132 + b2n + e]     = splitpack(a0p[e], b0p[e]);
            B2u[b2kp * 132 + b2n + 4 + e] = splitpack(a1p[e], b1p[e]);
        }
    }
    __syncthreads();

    // ================= GEMM2: Out[64,512] = Y[64,32] @ f2slc[32,512] =======
    for (int nc = 0; nc < 4; ++nc) {
        // prefetch next nc
        if (nc < 3) {
            const float* fp = f2b + (nc + 1) * 128;
            pa0 = __ldg((const float4*)fp);
            pa1 = __ldg((const float4*)(fp + 4));
            pb0 = __ldg((const float4*)(fp + DDIM));
            pb1 = __ldg((const float4*)(fp + DDIM + 4));
        }

        // compute 8 n-tiles of 8; immediate atomic scatter
        #pragma unroll 2
        for (int nt = 0; nt < 8; ++nt) {
            const int n0 = nhb * 64 + nt * 8;
            float acc[4] = {0.f, 0.f, 0.f, 0.f};
            #pragma unroll
            for (int s = 0; s < 2; ++s) {
                const int kp = s * 8 + c4;
                const ull b0 = B2u[kp * 132 + n0 + gq];
                const ull b1 = B2u[(kp + 4) * 132 + n0 + gq];
                mma16(acc, ulo(y0[s]), ulo(y1[s]), ulo(y2[s]), ulo(y3[s]), ulo(b0), ulo(b1));
                mma16(acc, ulo(y0[s]), ulo(y1[s]), ulo(y2[s]), ulo(y3[s]), uhi(b0), uhi(b1));
                mma16(acc, uhi(y0[s]), uhi(y1[s]), uhi(y2[s]), uhi(y3[s]), ulo(b0), ulo(b1));
            }
            const int d = nc * 128 + n0 + 2 * c4;
            atomicAdd((float2*)(out + rowb[m0 + gq]     + d), make_float2(acc[0], acc[1]));
            atomicAdd((float2*)(out + rowb[m0 + 8 + gq] + d), make_float2(acc[2], acc[3]));
        }
        __syncthreads();   // compute done before restage

        if (nc < 3) {
            const float* a0p = (const float*)&pa0;
            const float* a1p = (const float*)&pa1;
            const float* b0p = (const float*)&pb0;
            const float* b1p = (const float*)&pb1;
            #pragma unroll
            for (int e = 0; e < 4; ++e) {
                B2u[b2kp * 132 + b2n + e]     = splitpack(a0p[e], b0p[e]);
                B2u[b2kp * 132 + b2n + 4 + e] = splitpack(a1p[e], b1p[e]);
            }
            __syncthreads();
        }
    }
}

// ---------------------------------------------------------------------------
extern "C" void kernel_launch(void* const* d_in, const int* in_sizes, int n_in,
                              void* d_out, int out_size)
{
    (void)in_sizes; (void)n_in; (void)out_size;
    const float* x    = (const float*)d_in[0];
    const float* ctrl = (const float*)d_in[1];
    const float* f1   = (const float*)d_in[2];
    const float* f2   = (const float*)d_in[3];
    float* out = (float*)d_out;

    const int smem1 = 13312 * 4 + 2048;   // 55296
    cudaFuncSetAttribute(k_route,  cudaFuncAttributeMaxDynamicSharedMemorySize, smem1);
    cudaFuncSetAttribute(k_expert, cudaFuncAttributeMaxDynamicSharedMemorySize, SMEM2);

    k_route<<<NGROUPS, 256, smem1>>>(x, ctrl, out);
    k_expert<<<dim3(8, 64), 256, SMEM2>>>(x, f1, f2, out);
}

// round 11
// speedup vs baseline: 1.6997x; 1.0219x over previous
#include <cuda_runtime.h>
#include <cstdint>

#define NGROUPS 512   // B*S/16
#define NSLOTS  64    // E*Sets
#define DDIM    512
#define TTOK    16
#define FDIM    32

typedef unsigned long long ull;
union U2 { ull u; float2 f; };

// packed fp32x2 FMA (route kernel)
__device__ __forceinline__ void ffma2(ull& d, ull a, ull b) {
    asm("fma.rn.f32x2 %0, %1, %2, %0;" : "+l"(d) : "l"(a), "l"(b));
}
__device__ __forceinline__ ull bcast2(float x) {
    ull r; asm("mov.b64 %0, {%1, %1};" : "=l"(r) : "f"(x)); return r;
}

__device__ int g_winners[NGROUPS * NSLOTS];

// ---------------------------------------------------------------------------
// bf16 split helpers
// ---------------------------------------------------------------------------
__device__ __forceinline__ uint32_t bf2_of(float v0, float v1) {
    uint32_t r;
    asm("cvt.rn.bf16x2.f32 %0, %1, %2;" : "=r"(r) : "f"(v1), "f"(v0));
    return r;
}
// split (v0,v1) into bf16 hi-pair (low32) and residual lo-pair (high32)
__device__ __forceinline__ ull splitpack(float v0, float v1) {
    const uint32_t h = bf2_of(v0, v1);
    const float r0 = v0 - __uint_as_float(h << 16);
    const float r1 = v1 - __uint_as_float(h & 0xffff0000u);
    const uint32_t l = bf2_of(r0, r1);
    return (ull)h | ((ull)l << 32);
}
__device__ __forceinline__ void mma16(float* c, uint32_t a0, uint32_t a1,
                                      uint32_t a2, uint32_t a3,
                                      uint32_t b0, uint32_t b1) {
    asm volatile("mma.sync.aligned.m16n8k16.row.col.f32.bf16.bf16.f32 "
                 "{%0,%1,%2,%3}, {%4,%5,%6,%7}, {%8,%9}, {%0,%1,%2,%3};"
                 : "+f"(c[0]), "+f"(c[1]), "+f"(c[2]), "+f"(c[3])
                 : "r"(a0), "r"(a1), "r"(a2), "r"(a3), "r"(b0), "r"(b1));
}
__device__ __forceinline__ uint32_t ulo(ull v) { return (uint32_t)v; }
__device__ __forceinline__ uint32_t uhi(ull v) { return (uint32_t)(v >> 32); }

// ---------------------------------------------------------------------------
// Kernel 1: routing (unchanged — proven exact; zero-inits out).
// ---------------------------------------------------------------------------
__global__ __launch_bounds__(256) void k_route(const float* __restrict__ x,
                                               const float* __restrict__ ctrl,
                                               float* __restrict__ out)
{
    extern __shared__ float sm[];
    float* xs   = sm;
    float* part = sm + 8192;
    float* ls   = sm + 12288;
    double* dred = (double*)(sm + 13312);
    __shared__ int sflags[64];
    __shared__ int swin[64];
    __shared__ int snf;
    __shared__ double dlog[16];

    const int G   = blockIdx.x;
    const int tid = threadIdx.x;
    if (tid == 0) snf = 0;

    const float4* src = (const float4*)(x + (size_t)G * 8192);
    float4* dst = (float4*)(out + (size_t)G * 8192);
    float4* xs4 = (float4*)xs;
    const float4 z4 = make_float4(0.f, 0.f, 0.f, 0.f);
    for (int i = tid; i < 2048; i += 256) { xs4[i] = src[i]; dst[i] = z4; }
    __syncthreads();

    {
        const int sq = tid & 15;
        const int tq = (tid >> 4) & 3;
        const int ks = tid >> 6;
        const int kbase = ks * 128;
        U2 acc[4][2];
        #pragma unroll
        for (int t = 0; t < 4; ++t) { acc[t][0].u = 0ull; acc[t][1].u = 0ull; }
        const float* cbase = ctrl + sq * 4;
        const float* x0 = xs + tq * 4 * DDIM;
        for (int kk = 0; kk < 128; kk += 4) {
            const int k = kbase + kk;
            ulonglong2 w[4];
            #pragma unroll
            for (int j = 0; j < 4; ++j)
                w[j] = __ldg((const ulonglong2*)(cbase + (size_t)(k + j) * 64));
            float xv[4][4];
            #pragma unroll
            for (int t = 0; t < 4; ++t)
                *(float4*)&xv[t][0] = *(const float4*)(x0 + t * DDIM + k);
            #pragma unroll
            for (int j = 0; j < 4; ++j) {
                #pragma unroll
                for (int t = 0; t < 4; ++t) {
                    ull xb = bcast2(xv[t][j]);
                    ffma2(acc[t][0].u, xb, w[j].x);
                    ffma2(acc[t][1].u, xb, w[j].y);
                }
            }
        }
        #pragma unroll
        for (int t = 0; t < 4; ++t) {
            part[tid * 16 + t * 4 + 0] = acc[t][0].f.x;
            part[tid * 16 + t * 4 + 1] = acc[t][0].f.y;
            part[tid * 16 + t * 4 + 2] = acc[t][1].f.x;
            part[tid * 16 + t * 4 + 3] = acc[t][1].f.y;
        }
    }
    __syncthreads();

    {
        const int s   = tid & 63;
        const int tq2 = tid >> 6;
        const int sq2 = s >> 2, sl = s & 3;
        const float step = 1e-6f / 15.f;
        #pragma unroll
        for (int tl = 0; tl < 4; ++tl) {
            float v = 0.f;
            #pragma unroll
            for (int c = 0; c < 4; ++c)
                v += part[(c * 64 + tq2 * 16 + sq2) * 16 + tl * 4 + sl];
            const int t = tq2 * 4 + tl;
            ls[s * 16 + t] = v + step * (float)t;
        }
    }
    __syncthreads();

    if (tid < 64) {
        const int s = tid;
        float best = -3.4e38f, second = -3.4e38f;
        int bi = 0;
        #pragma unroll
        for (int t = 0; t < TTOK; ++t) {
            float v = ls[s * 16 + t];
            if (v >= best) { second = best; best = v; bi = t; }
            else if (v > second) { second = v; }
        }
        swin[s] = bi;
        if (best - second < 2e-5f) { int p = atomicAdd(&snf, 1); sflags[p] = s; }
    }
    __syncthreads();

    const int nf = snf;
    for (int i = 0; i < nf; ++i) {
        const int s = sflags[i];
        const int t = tid >> 4, j = tid & 15;
        double a = 0.0;
        const float* xr = xs + t * DDIM + j * 32;
        const float* cp = ctrl + (size_t)(j * 32) * 64 + s;
        #pragma unroll 8
        for (int k = 0; k < 32; ++k)
            a += (double)xr[k] * (double)__ldg(cp + (size_t)k * 64);
        dred[t * 16 + j] = a;
        __syncthreads();
        if (tid < 16) {
            double tot = 0.0;
            #pragma unroll
            for (int j2 = 0; j2 < 16; ++j2) tot += dred[tid * 16 + j2];
            dlog[tid] = tot + (double)tid * (1e-6 / 15.0);
        }
        __syncthreads();
        if (tid == 0) {
            double best = -1e300; int bi = 0;
            #pragma unroll
            for (int t2 = 0; t2 < TTOK; ++t2)
                if (dlog[t2] >= best) { best = dlog[t2]; bi = t2; }
            swin[s] = bi;
        }
        __syncthreads();
    }
    if (tid < 64) g_winners[G * 64 + tid] = swin[tid];
}

// ---------------------------------------------------------------------------
// Kernel 2: split-bf16 mma.sync expert, 128 threads / 4 warps, 64 rows/CTA.
// Warp = one 16-row m-tile, ALL 32 f (GEMM1) and ALL 512 n (GEMM2).
// GEMM1 C-fragments are reused IN REGISTERS as GEMM2 A-fragments (relu+split
// in regs) — Y never touches smem. Double-buffered X/B1 and B2 staging with
// one __syncthreads per chunk. X global loads row-contiguous (4 lines/instr).
// Smem (bytes): rowb @0 (256); B1buf[2] @256, each [32 kp][36] ull (9216);
// Xbuf[2] @18688, each [64 row][36] ull (18432); B2buf[2] aliases Xbuf,
// each [16 kp][132] ull (16896). Total 55552.
// ---------------------------------------------------------------------------
#define OFF_ROWB 0
#define OFF_B1   256
#define OFF_X    18688
#define SMEM2    55552

__global__ __launch_bounds__(128, 4) void k_expert(const float* __restrict__ x,
                                                   const float* __restrict__ f1,
                                                   const float* __restrict__ f2,
                                                   float* __restrict__ out)
{
    extern __shared__ __align__(16) char smraw[];
    int* rowb = (int*)(smraw + OFF_ROWB);
    ull* B1b  = (ull*)(smraw + OFF_B1);   // [2][32*36]
    ull* Xb   = (ull*)(smraw + OFF_X);    // [2][64*36]
    ull* B2b  = (ull*)(smraw + OFF_X);    // [2][16*132] alias

    const int slot = blockIdx.y;
    const int g0   = blockIdx.x * 64;
    const int tid  = threadIdx.x;
    const int wid  = tid >> 5;
    const int lane = tid & 31;
    const int gq   = lane >> 2;   // fragment row group 0..7
    const int c4   = lane & 3;    // fragment col group 0..3

    if (tid < 64) {
        const int gg = g0 + tid;
        rowb[tid] = (gg * TTOK + g_winners[gg * 64 + slot]) * DDIM;
    }
    __syncthreads();

    const int m0 = wid * 16;

    // ---- staging maps
    const int xr0 = tid >> 4;          // X: base row 0..7 (rows xr0+8p)
    const int xf4 = tid & 15;          // X: float4 index within 64-k chunk
    const int bkp = tid >> 2;          // B1: k-pair 0..31
    const int bfq = (tid & 3) * 8;     // B1: f base (8 f)
    const float* f1b = f1 + slot * 32 + bfq;
    const int b2kp = tid >> 3;         // B2: f-pair 0..15
    const int b2n  = (tid & 7) * 16;   // B2: n base (16 n)
    const float* f2b = f2 + (size_t)slot * (FDIM * DDIM)
                     + (size_t)(2 * b2kp) * DDIM + b2n;

    // ---- prefetch chunk 0
    float4 xv[8];
    float4 w0a, w0b, w1a, w1b;
    #pragma unroll
    for (int p = 0; p < 8; ++p)
        xv[p] = __ldg((const float4*)(x + rowb[xr0 + 8 * p] + xf4 * 4));
    {
        const float* r0 = f1b + (size_t)(2 * bkp) * 2048;
        const float* r1 = f1b + (size_t)(2 * bkp + 1) * 2048;
        w0a = __ldg((const float4*)r0);
        w0b = __ldg((const float4*)(r0 + 4));
        w1a = __ldg((const float4*)r1);
        w1b = __ldg((const float4*)(r1 + 4));
    }
    // stage chunk 0 into buf 0
    {
        ull* Xu = Xb;
        #pragma unroll
        for (int p = 0; p < 8; ++p) {
            ulonglong2 w;
            w.x = splitpack(xv[p].x, xv[p].y);
            w.y = splitpack(xv[p].z, xv[p].w);
            *(ulonglong2*)&Xu[(xr0 + 8 * p) * 36 + 2 * xf4] = w;
        }
        ull* B1u = B1b;
        const float* ka0 = (const float*)&w0a;
        const float* ka1 = (const float*)&w0b;
        const float* kb0 = (const float*)&w1a;
        const float* kb1 = (const float*)&w1b;
        #pragma unroll
        for (int e = 0; e < 4; e += 2) {
            ulonglong2 wa, wb;
            wa.x = splitpack(ka0[e],     kb0[e]);
            wa.y = splitpack(ka0[e + 1], kb0[e + 1]);
            wb.x = splitpack(ka1[e],     kb1[e]);
            wb.y = splitpack(ka1[e + 1], kb1[e + 1]);
            *(ulonglong2*)&B1u[bkp * 36 + bfq + e] = wa;
            *(ulonglong2*)&B1u[bkp * 36 + bfq + 4 + e] = wb;
        }
    }
    __syncthreads();

    float acc1[4][4];
    #pragma unroll
    for (int j = 0; j < 4; ++j)
        #pragma unroll
        for (int e = 0; e < 4; ++e) acc1[j][e] = 0.f;

    // ================= GEMM1: C[64,32] = X[64,512] @ f1slc[512,32] =========
    for (int cb = 0; cb < 8; ++cb) {
        // prefetch chunk cb+1
        if (cb < 7) {
            const int kb = (cb + 1) * 64;
            #pragma unroll
            for (int p = 0; p < 8; ++p)
                xv[p] = __ldg((const float4*)(x + rowb[xr0 + 8 * p] + kb + xf4 * 4));
            const float* r0 = f1b + (size_t)(kb + 2 * bkp) * 2048;
            const float* r1 = f1b + (size_t)(kb + 2 * bkp + 1) * 2048;
            w0a = __ldg((const float4*)r0);
            w0b = __ldg((const float4*)(r0 + 4));
            w1a = __ldg((const float4*)r1);
            w1b = __ldg((const float4*)(r1 + 4));
        }

        // compute chunk cb
        const ull* Xu  = Xb  + (cb & 1) * 2304;
        const ull* B1u = B1b + (cb & 1) * 1152;
        #pragma unroll
        for (int s = 0; s < 4; ++s) {
            const int kp = s * 8 + c4;
            const ull a0 = Xu[(m0 + gq) * 36 + kp];
            const ull a1 = Xu[(m0 + 8 + gq) * 36 + kp];
            const ull a2 = Xu[(m0 + gq) * 36 + kp + 4];
            const ull a3 = Xu[(m0 + 8 + gq) * 36 + kp + 4];
            #pragma unroll
            for (int j = 0; j < 4; ++j) {
                const ull b0 = B1u[kp * 36 + j * 8 + gq];
                const ull b1 = B1u[(kp + 4) * 36 + j * 8 + gq];
                mma16(acc1[j], ulo(a0), ulo(a1), ulo(a2), ulo(a3), ulo(b0), ulo(b1));
                mma16(acc1[j], ulo(a0), ulo(a1), ulo(a2), ulo(a3), uhi(b0), uhi(b1));
                mma16(acc1[j], uhi(a0), uhi(a1), uhi(a2), uhi(a3), ulo(b0), ulo(b1));
            }
        }

        // stage chunk cb+1 into the other buffer
        if (cb < 7) {
            ull* Xu2  = Xb  + ((cb + 1) & 1) * 2304;
            ull* B1u2 = B1b + ((cb + 1) & 1) * 1152;
            #pragma unroll
            for (int p = 0; p < 8; ++p) {
                ulonglong2 w;
                w.x = splitpack(xv[p].x, xv[p].y);
                w.y = splitpack(xv[p].z, xv[p].w);
                *(ulonglong2*)&Xu2[(xr0 + 8 * p) * 36 + 2 * xf4] = w;
            }
            const float* ka0 = (const float*)&w0a;
            const float* ka1 = (const float*)&w0b;
            const float* kb0 = (const float*)&w1a;
            const float* kb1 = (const float*)&w1b;
            #pragma unroll
            for (int e = 0; e < 4; e += 2) {
                ulonglong2 wa, wb;
                wa.x = splitpack(ka0[e],     kb0[e]);
                wa.y = splitpack(ka0[e + 1], kb0[e + 1]);
                wb.x = splitpack(ka1[e],     kb1[e]);
                wb.y = splitpack(ka1[e + 1], kb1[e + 1]);
                *(ulonglong2*)&B1u2[bkp * 36 + bfq + e] = wa;
                *(ulonglong2*)&B1u2[bkp * 36 + bfq + 4 + e] = wb;
            }
        }
        __syncthreads();
    }

    // ---- relu + split IN REGISTERS -> GEMM2 A-fragments -------------------
    // For k16-step s over f: a0/a1 from n-tile 2s, a2/a3 from n-tile 2s+1.
    uint32_t yh[2][4], yl[2][4];
    #pragma unroll
    for (int s = 0; s < 2; ++s) {
        const int j0 = 2 * s, j1 = 2 * s + 1;
        ull p;
        p = splitpack(fmaxf(acc1[j0][0], 0.f), fmaxf(acc1[j0][1], 0.f));
        yh[s][0] = ulo(p); yl[s][0] = uhi(p);
        p = splitpack(fmaxf(acc1[j0][2], 0.f), fmaxf(acc1[j0][3], 0.f));
        yh[s][1] = ulo(p); yl[s][1] = uhi(p);
        p = splitpack(fmaxf(acc1[j1][0], 0.f), fmaxf(acc1[j1][1], 0.f));
        yh[s][2] = ulo(p); yl[s][2] = uhi(p);
        p = splitpack(fmaxf(acc1[j1][2], 0.f), fmaxf(acc1[j1][3], 0.f));
        yh[s][3] = ulo(p); yl[s][3] = uhi(p);
    }

    // per-thread output row offsets
    const int ro0 = rowb[m0 + gq];
    const int ro1 = rowb[m0 + 8 + gq];

    // ---- prefetch B2 chunk nc=0
    float4 pv[8];
    #pragma unroll
    for (int q = 0; q < 4; ++q) {
        pv[q]     = __ldg((const float4*)(f2b + q * 4));
        pv[4 + q] = __ldg((const float4*)(f2b + DDIM + q * 4));
    }
    __syncthreads();   // all X reads (chunk 7) done before overwriting alias

    // stage B2 nc=0 into buf 0
    {
        ull* B2u = B2b;
        const float* lo = (const float*)&pv[0];
        const float* hi = (const float*)&pv[4];
        #pragma unroll
        for (int e = 0; e < 16; e += 2) {
            ulonglong2 w;
            w.x = splitpack(lo[e],     hi[e]);
            w.y = splitpack(lo[e + 1], hi[e + 1]);
            *(ulonglong2*)&B2u[b2kp * 132 + b2n + e] = w;
        }
    }
    __syncthreads();

    // ================= GEMM2: Out[64,512] = Y[64,32] @ f2slc[32,512] =======
    for (int nc = 0; nc < 4; ++nc) {
        // prefetch next nc
        if (nc < 3) {
            const float* fp = f2b + (nc + 1) * 128;
            #pragma unroll
            for (int q = 0; q < 4; ++q) {
                pv[q]     = __ldg((const float4*)(fp + q * 4));
                pv[4 + q] = __ldg((const float4*)(fp + DDIM + q * 4));
            }
        }

        const ull* B2u = B2b + (nc & 1) * 2112;
        #pragma unroll 2
        for (int nt = 0; nt < 16; ++nt) {
            const int n0 = nt * 8;
            float acc[4] = {0.f, 0.f, 0.f, 0.f};
            #pragma unroll
            for (int s = 0; s < 2; ++s) {
                const int kp = s * 8 + c4;
                const ull b0 = B2u[kp * 132 + n0 + gq];
                const ull b1 = B2u[(kp + 4) * 132 + n0 + gq];
                mma16(acc, yh[s][0], yh[s][1], yh[s][2], yh[s][3], ulo(b0), ulo(b1));
                mma16(acc, yh[s][0], yh[s][1], yh[s][2], yh[s][3], uhi(b0), uhi(b1));
                mma16(acc, yl[s][0], yl[s][1], yl[s][2], yl[s][3], ulo(b0), ulo(b1));
            }
            const int d = nc * 128 + n0 + 2 * c4;
            atomicAdd((float2*)(out + ro0 + d), make_float2(acc[0], acc[1]));
            atomicAdd((float2*)(out + ro1 + d), make_float2(acc[2], acc[3]));
        }

        // stage next nc into the other buffer
        if (nc < 3) {
            ull* B2u2 = B2b + ((nc + 1) & 1) * 2112;
            const float* lo = (const float*)&pv[0];
            const float* hi = (const float*)&pv[4];
            #pragma unroll
            for (int e = 0; e < 16; e += 2) {
                ulonglong2 w;
                w.x = splitpack(lo[e],     hi[e]);
                w.y = splitpack(lo[e + 1], hi[e + 1]);
                *(ulonglong2*)&B2u2[b2kp * 132 + b2n + e] = w;
            }
        }
        __syncthreads();
    }
}

// ---------------------------------------------------------------------------
extern "C" void kernel_launch(void* const* d_in, const int* in_sizes, int n_in,
                              void* d_out, int out_size)
{
    (void)in_sizes; (void)n_in; (void)out_size;
    const float* x    = (const float*)d_in[0];
    const float* ctrl = (const float*)d_in[1];
    const float* f1   = (const float*)d_in[2];
    const float* f2   = (const float*)d_in[3];
    float* out = (float*)d_out;

    const int smem1 = 13312 * 4 + 2048;   // 55296
    cudaFuncSetAttribute(k_route,  cudaFuncAttributeMaxDynamicSharedMemorySize, smem1);
    cudaFuncSetAttribute(k_expert, cudaFuncAttributeMaxDynamicSharedMemorySize, SMEM2);

    k_route<<<NGROUPS, 256, smem1>>>(x, ctrl, out);
    k_expert<<<dim3(8, 64), 128, SMEM2>>>(x, f1, f2, out);
}